// round 4
// baseline (speedup 1.0000x reference)
#include <cuda_runtime.h>
#include <cuda_bf16.h>
#include <math.h>

#define BATCH 64
#define SEQ   512
#define EMB   128
#define HID   256
#define H4    1024
#define TAGS  9

// static scratch (no runtime allocation)
__device__ float g_xz[2][SEQ][BATCH][H4];          // per-direction xz[t][b][1024]
__device__ float g_hall[BATCH * SEQ * 2 * HID];    // [b*S+t][h_fwd|h_bwd]

__device__ __forceinline__ float sigmoid_f(float x) {
    return __fdividef(1.0f, 1.0f + __expf(-x));
}
__device__ __forceinline__ float tanh_f(float x) {
    return 1.0f - __fdividef(2.0f, __expf(2.0f * x) + 1.0f);
}
__device__ __forceinline__ void fma2(unsigned long long& a, unsigned long long b,
                                     unsigned long long c) {
    asm("fma.rn.f32x2 %0, %1, %2, %0;" : "+l"(a) : "l"(b), "l"(c));
}
__device__ __forceinline__ unsigned long long dupf2(float x) {
    unsigned long long r;
    unsigned u = __float_as_uint(x);
    asm("mov.b64 %0, {%1, %1};" : "=l"(r) : "r"(u));
    return r;
}

// ---------------------------------------------------------------------------
// Phase 1: xz = emb[text] @ [W_f|W_b] + bias.  M=32768, N=2048, K=128
// ---------------------------------------------------------------------------
__global__ __launch_bounds__(256) void gemm_xz_kernel(
    const int* __restrict__ text, const float* __restrict__ emb,
    const float* __restrict__ Wf, const float* __restrict__ Wb,
    const float* __restrict__ bf, const float* __restrict__ bb)
{
    __shared__ float As[16][128];
    __shared__ float Ws[16][64];
    __shared__ int   toks[128];

    const int m0 = blockIdx.y * 128;
    const int n0 = blockIdx.x * 64;
    const int tid = threadIdx.x;

    if (tid < 128) toks[tid] = text[m0 + tid];
    __syncthreads();

    const float* W = (n0 < H4) ? Wf : Wb;
    const int nw0 = n0 & (H4 - 1);
    const int tx = tid & 15;
    const int ty = tid >> 4;

    unsigned long long acc2[4][4];
#pragma unroll
    for (int i = 0; i < 4; i++)
#pragma unroll
        for (int j = 0; j < 4; j++) acc2[i][j] = 0ull;

    for (int k0 = 0; k0 < EMB; k0 += 16) {
#pragma unroll
        for (int q = 0; q < 2; q++) {
            int id = tid * 2 + q;
            int row = id >> 2, kq = id & 3;
            float4 v = *reinterpret_cast<const float4*>(&emb[toks[row] * EMB + k0 + kq * 4]);
            As[kq * 4 + 0][row] = v.x;
            As[kq * 4 + 1][row] = v.y;
            As[kq * 4 + 2][row] = v.z;
            As[kq * 4 + 3][row] = v.w;
        }
        {
            int k = tid >> 4, n4 = (tid & 15) * 4;
            *reinterpret_cast<float4*>(&Ws[k][n4]) =
                *reinterpret_cast<const float4*>(&W[(k0 + k) * H4 + nw0 + n4]);
        }
        __syncthreads();

#pragma unroll
        for (int k = 0; k < 16; k++) {
            ulonglong2 a01 = *reinterpret_cast<const ulonglong2*>(&As[k][ty * 8]);
            ulonglong2 a23 = *reinterpret_cast<const ulonglong2*>(&As[k][ty * 8 + 4]);
            float4 w4 = *reinterpret_cast<const float4*>(&Ws[k][tx * 4]);
            unsigned long long ap[4] = {a01.x, a01.y, a23.x, a23.y};
            unsigned long long wd[4] = {dupf2(w4.x), dupf2(w4.y), dupf2(w4.z), dupf2(w4.w)};
#pragma unroll
            for (int i = 0; i < 4; i++)
#pragma unroll
                for (int j = 0; j < 4; j++) fma2(acc2[i][j], ap[i], wd[j]);
        }
        __syncthreads();
    }

    const float* bias = (n0 < H4) ? bf : bb;
    const int d = (n0 < H4) ? 0 : 1;
    const int col = nw0 + tx * 4;
    float4 bv = *reinterpret_cast<const float4*>(&bias[col]);

#pragma unroll
    for (int i = 0; i < 4; i++) {
#pragma unroll
        for (int half = 0; half < 2; half++) {
            int gm = m0 + ty * 8 + 2 * i + half;
            int b = gm >> 9, t = gm & (SEQ - 1);
            float4 v;
            unsigned lo, hi;
            asm("mov.b64 {%0, %1}, %2;" : "=r"(lo), "=r"(hi) : "l"(acc2[i][0]));
            v.x = __uint_as_float(half ? hi : lo) + bv.x;
            asm("mov.b64 {%0, %1}, %2;" : "=r"(lo), "=r"(hi) : "l"(acc2[i][1]));
            v.y = __uint_as_float(half ? hi : lo) + bv.y;
            asm("mov.b64 {%0, %1}, %2;" : "=r"(lo), "=r"(hi) : "l"(acc2[i][2]));
            v.z = __uint_as_float(half ? hi : lo) + bv.z;
            asm("mov.b64 {%0, %1}, %2;" : "=r"(lo), "=r"(hi) : "l"(acc2[i][3]));
            v.w = __uint_as_float(half ? hi : lo) + bv.w;
            *reinterpret_cast<float4*>(&g_xz[d][t][b][col]) = v;
        }
    }
}

// ---------------------------------------------------------------------------
// Phase 2: persistent bidirectional LSTM. 16 clusters x 8 CTAs (128 SMs).
// U slice register-resident (128 regs/thread). thread = (column c, K-half).
// Row-pair f32x2 accumulation against transposed h buffer hT[k][8 rows].
// h exchanged via DSMEM push + one cluster barrier per step.
// ---------------------------------------------------------------------------
__global__ void __cluster_dims__(8, 1, 1) __launch_bounds__(256, 1)
lstm_kernel(const float* __restrict__ Uf, const float* __restrict__ Ub)
{
    __shared__ float hT[2][256][8];   // [buf][unit k][row]
    __shared__ float zsh[8][256];     // [(kh*4+rp)][2c + (r&1)]

    const int tid = threadIdx.x;
    const int cb  = blockIdx.x & 7;   // cluster rank = 32-unit column block
    const int cid = blockIdx.x >> 3;
    const int d   = cid >> 3;         // direction
    const int bb  = cid & 7;          // batch block (8 rows)
    const float* U = d ? Ub : Uf;

    // register-resident U column slice
    const int c  = tid & 127;         // gate column 0..127
    const int kh = tid >> 7;          // K-half
    const int gcol = ((c >> 5) << 8) + (cb << 5) + (c & 31);
    float Ureg[128];
#pragma unroll
    for (int j = 0; j < 128; j++)
        Ureg[j] = __ldg(&U[(kh * 128 + j) * H4 + gcol]);

    for (int i = tid; i < 256 * 8; i += 256) (&hT[0][0][0])[i] = 0.0f;
    __syncthreads();
    asm volatile("barrier.cluster.arrive.aligned;" ::: "memory");
    asm volatile("barrier.cluster.wait.aligned;" ::: "memory");

    // gate-phase mapping
    const int rB = tid >> 5;          // batch row within block
    const int uB = tid & 31;          // unit within 32-block
    const int rp = rB >> 1;           // row pair
    const int pe = rB & 1;            // parity within pair
    const int bglob = bb * 8 + rB;
    const unsigned hbase = (unsigned)__cvta_generic_to_shared(&hT[0][0][0]);
    float cell = 0.0f;
    int cur = 0;

    for (int t = 0; t < SEQ; t++) {
        const int tt = d ? (SEQ - 1 - t) : t;

        // prefetch xz for this thread's 4 gates (consumed after GEMM)
        const float* xzp = &g_xz[d][tt][bglob][(cb << 5) + uB];
        const float xi = __ldg(xzp);
        const float xf = __ldg(xzp + 256);
        const float xg = __ldg(xzp + 512);
        const float xo = __ldg(xzp + 768);

        // GEMM: z[r][c] partial over K-half. acc pairs = rows (0,1),(2,3),(4,5),(6,7)
        unsigned long long a01 = 0ull, a23 = 0ull, a45 = 0ull, a67 = 0ull;
        const float* hp = &hT[cur][kh * 128][0];
#pragma unroll
        for (int k = 0; k < 128; k++) {
            ulonglong2 hv = *reinterpret_cast<const ulonglong2*>(&hp[k * 8]);     // r0..r3
            ulonglong2 hw = *reinterpret_cast<const ulonglong2*>(&hp[k * 8 + 4]); // r4..r7
            unsigned long long ud = dupf2(Ureg[k]);
            fma2(a01, ud, hv.x);
            fma2(a23, ud, hv.y);
            fma2(a45, ud, hw.x);
            fma2(a67, ud, hw.y);
        }
        *reinterpret_cast<unsigned long long*>(&zsh[kh * 4 + 0][2 * c]) = a01;
        *reinterpret_cast<unsigned long long*>(&zsh[kh * 4 + 1][2 * c]) = a23;
        *reinterpret_cast<unsigned long long*>(&zsh[kh * 4 + 2][2 * c]) = a45;
        *reinterpret_cast<unsigned long long*>(&zsh[kh * 4 + 3][2 * c]) = a67;
        __syncthreads();

        // gates: thread -> (row rB, unit uB); z[rB][g*32+uB] = kh0 + kh1 partials
        const int q0 = 2 * uB + pe;   // within gate block, interleaved pairs
        const float zi = zsh[rp][q0 +   0] + zsh[4 + rp][q0 +   0] + xi;
        const float zf = zsh[rp][q0 +  64] + zsh[4 + rp][q0 +  64] + xf;
        const float zg = zsh[rp][q0 + 128] + zsh[4 + rp][q0 + 128] + xg;
        const float zo = zsh[rp][q0 + 192] + zsh[4 + rp][q0 + 192] + xo;
        const float ig = sigmoid_f(zi);
        const float fg = sigmoid_f(zf);
        const float gg = tanh_f(zg);
        const float og = sigmoid_f(zo);
        cell = fg * cell + ig * gg;
        const float h = og * tanh_f(cell);

        g_hall[(bglob * SEQ + tt) * (2 * HID) + d * HID + (cb << 5) + uB] = h;

        // push h to all 8 cluster CTAs' next hT buffer: element [nxt][cb*32+uB][rB]
        const int nxt = cur ^ 1;
        const unsigned off = hbase +
            (unsigned)(((nxt * 256 + (cb << 5) + uB) * 8 + rB) * 4);
#pragma unroll
        for (int p = 0; p < 8; p++) {
            asm volatile(
                "{ .reg .b32 r; mapa.shared::cluster.u32 r, %0, %1;"
                "  st.shared::cluster.f32 [r], %2; }"
                :: "r"(off), "r"(p), "f"(h) : "memory");
        }

        asm volatile("barrier.cluster.arrive.aligned;" ::: "memory");
        asm volatile("barrier.cluster.wait.aligned;" ::: "memory");
        cur = nxt;
    }
}

// ---------------------------------------------------------------------------
// Phase 3: logits = h_all @ W_d + b_d   (warp per row-group)
// ---------------------------------------------------------------------------
__global__ __launch_bounds__(256) void decoder_kernel(
    const float* __restrict__ Wd, const float* __restrict__ bd,
    float* __restrict__ out)
{
    __shared__ float Ws[2 * HID * TAGS];
    __shared__ float bs[TAGS];
    const int tid = threadIdx.x;
    for (int i = tid; i < 2 * HID * TAGS; i += 256) Ws[i] = Wd[i];
    if (tid < TAGS) bs[tid] = bd[tid];
    __syncthreads();

    const int w = tid >> 5, lane = tid & 31;
    const int wg = blockIdx.x * 8 + w;

    for (int rr = 0; rr < 16; rr++) {
        const int row = wg * 16 + rr;
        const float* hp = &g_hall[row * (2 * HID)];
        float p[TAGS];
#pragma unroll
        for (int j = 0; j < TAGS; j++) p[j] = 0.0f;
#pragma unroll
        for (int e = 0; e < 16; e++) {
            const int k = e * 32 + lane;
            const float hv = __ldg(&hp[k]);
#pragma unroll
            for (int j = 0; j < TAGS; j++) p[j] += hv * Ws[k * TAGS + j];
        }
#pragma unroll
        for (int j = 0; j < TAGS; j++)
#pragma unroll
            for (int off = 16; off; off >>= 1)
                p[j] += __shfl_xor_sync(0xffffffffu, p[j], off);
        if (lane < TAGS) out[row * TAGS + lane] = p[lane] + bs[lane];
    }
}

// ---------------------------------------------------------------------------
// Phase 4: lens + CRF sequence score + log-norm. One warp per batch row.
// ---------------------------------------------------------------------------
__global__ __launch_bounds__(32) void crf_kernel(
    const int* __restrict__ text, const int* __restrict__ labels,
    const float* __restrict__ trans, const float* __restrict__ logits,
    float* __restrict__ out_lens, float* __restrict__ out_ll)
{
    __shared__ float lg[SEQ * TAGS];
    __shared__ int   lb[SEQ];
    __shared__ float tr[TAGS * TAGS];

    const int b = blockIdx.x;
    const int lane = threadIdx.x;
    const float* Lp = logits + b * SEQ * TAGS;

    for (int i = lane; i < SEQ * TAGS; i += 32) lg[i] = Lp[i];
    for (int i = lane; i < SEQ; i += 32) lb[i] = labels[b * SEQ + i];
    for (int i = lane; i < TAGS * TAGS; i += 32) tr[i] = trans[i];

    int cnt = 0;
    for (int t = lane; t < SEQ; t += 32) cnt += (text[b * SEQ + t] != 0);
#pragma unroll
    for (int off = 16; off; off >>= 1) cnt += __shfl_xor_sync(0xffffffffu, cnt, off);
    __syncthreads();
    const int len = cnt;

    float uny = 0.0f, bny = 0.0f;
    for (int t = lane; t < SEQ; t += 32)
        if (t < len) uny += lg[t * TAGS + lb[t]];
    for (int t = lane; t < SEQ - 1; t += 32)
        if (t < len - 1) bny += tr[lb[t] * TAGS + lb[t + 1]];
#pragma unroll
    for (int off = 16; off; off >>= 1) {
        uny += __shfl_xor_sync(0xffffffffu, uny, off);
        bny += __shfl_xor_sync(0xffffffffu, bny, off);
    }

    const int j = (lane < TAGS) ? lane : (TAGS - 1);
    float Tc[TAGS];
#pragma unroll
    for (int i = 0; i < TAGS; i++) Tc[i] = tr[i * TAGS + j];

    float a = lg[j];
    for (int t = 1; t < SEQ; t++) {
        float ai[TAGS];
#pragma unroll
        for (int i = 0; i < TAGS; i++) ai[i] = __shfl_sync(0xffffffffu, a, i);
        if (t < len) {
            float m = -1e30f;
#pragma unroll
            for (int i = 0; i < TAGS; i++) m = fmaxf(m, ai[i] + Tc[i]);
            float s = 0.0f;
#pragma unroll
            for (int i = 0; i < TAGS; i++) s += __expf(ai[i] + Tc[i] - m);
            a = m + __logf(s) + lg[t * TAGS + j];
        }
    }
    float av = (lane < TAGS) ? a : -1e30f;
    float m = av;
#pragma unroll
    for (int off = 16; off; off >>= 1) m = fmaxf(m, __shfl_xor_sync(0xffffffffu, m, off));
    float s = (lane < TAGS) ? __expf(av - m) : 0.0f;
#pragma unroll
    for (int off = 16; off; off >>= 1) s += __shfl_xor_sync(0xffffffffu, s, off);
    const float logZ = m + __logf(s);

    if (lane == 0) {
        out_lens[b] = (float)len;
        out_ll[b]   = uny + bny - logZ;
    }
}

// ---------------------------------------------------------------------------
extern "C" void kernel_launch(void* const* d_in, const int* in_sizes, int n_in,
                              void* d_out, int out_size) {
    const int*   text   = (const int*)  d_in[0];
    const int*   labels = (const int*)  d_in[1];
    const float* emb    = (const float*)d_in[2];
    const float* W_f    = (const float*)d_in[3];
    const float* U_f    = (const float*)d_in[4];
    const float* b_f    = (const float*)d_in[5];
    const float* W_b    = (const float*)d_in[6];
    const float* U_b    = (const float*)d_in[7];
    const float* b_b    = (const float*)d_in[8];
    const float* W_d    = (const float*)d_in[9];
    const float* b_d    = (const float*)d_in[10];
    const float* trans  = (const float*)d_in[11];
    float* out = (float*)d_out;

    gemm_xz_kernel<<<dim3(32, 256), 256>>>(text, emb, W_f, W_b, b_f, b_b);
    lstm_kernel<<<128, 256>>>(U_f, U_b);
    decoder_kernel<<<256, 256>>>(W_d, b_d, out);

    float* out_logits = out;                         // B*S*TAGS
    float* out_lens   = out + BATCH * SEQ * TAGS;    // 64
    float* out_ll     = out_lens + BATCH;            // 64
    crf_kernel<<<BATCH, 32>>>(text, labels, trans, out_logits, out_lens, out_ll);
}